// round 1
// baseline (speedup 1.0000x reference)
#include <cuda_runtime.h>
#include <math_constants.h>
#include <cstdint>

// ---------------- scratch (static device globals; no allocation) ----------------
__device__ float g_h1[8192u * 1024u];   // after layer 1
__device__ float g_h2[8192u * 512u];    // after layer 2
__device__ float g_p [8192u * 256u];    // projection
__device__ float g_pn[8192];            // row norms of p
__device__ float g_en[10000];           // row norms of emb

#define BM 128
#define BN 128
#define BK 8
#define TM 8
#define TN 8

// ---------------- generic SGEMM: C = act(A @ W + bias) ----------------
// A: [M,K] row-major (optionally split into two halves of width 768: concat)
// W: [K,N] row-major, bias: [N]
template<bool RELU, bool CONCAT>
__global__ void __launch_bounds__(256, 2) gemm_bias_kernel(
    const float* __restrict__ A, const float* __restrict__ A2,
    const float* __restrict__ W, const float* __restrict__ bias,
    float* __restrict__ C, int M, int N, int K)
{
    __shared__ float As[BK][BM];
    __shared__ float Ws[BK][BN];

    const int tid = threadIdx.x;
    const int tx = tid & 15;         // 0..15 -> col tile
    const int ty = tid >> 4;         // 0..15 -> row tile
    const int rowBase = blockIdx.y * BM;
    const int colBase = blockIdx.x * BN;

    // A-tile loader: 128 rows x 8 cols, one float4 per thread
    const int aRow = tid >> 1;           // 0..127
    const int aCol = (tid & 1) * 4;      // 0 or 4
    const int gArow = rowBase + aRow;
    // W-tile loader: 8 rows x 128 cols, one float4 per thread
    const int wRow = tid >> 5;           // 0..7
    const int wCol = (tid & 31) * 4;     // 0..124

    float acc[TM][TN];
    #pragma unroll
    for (int i = 0; i < TM; i++)
        #pragma unroll
        for (int j = 0; j < TN; j++) acc[i][j] = 0.f;

    for (int k0 = 0; k0 < K; k0 += BK) {
        float4 av;
        const int gk = k0 + aCol;
        if (CONCAT) {
            if (gk < 768) av = *(const float4*)&A [(size_t)gArow * 768 + gk];
            else          av = *(const float4*)&A2[(size_t)gArow * 768 + (gk - 768)];
        } else {
            av = *(const float4*)&A[(size_t)gArow * K + gk];
        }
        As[aCol + 0][aRow] = av.x;
        As[aCol + 1][aRow] = av.y;
        As[aCol + 2][aRow] = av.z;
        As[aCol + 3][aRow] = av.w;

        float4 wv = *(const float4*)&W[(size_t)(k0 + wRow) * N + colBase + wCol];
        *(float4*)&Ws[wRow][wCol] = wv;

        __syncthreads();

        #pragma unroll
        for (int k = 0; k < BK; k++) {
            float ar[TM], br[TN];
            *(float4*)&ar[0] = *(const float4*)&As[k][ty * TM];
            *(float4*)&ar[4] = *(const float4*)&As[k][ty * TM + 4];
            *(float4*)&br[0] = *(const float4*)&Ws[k][tx * TN];
            *(float4*)&br[4] = *(const float4*)&Ws[k][tx * TN + 4];
            #pragma unroll
            for (int i = 0; i < TM; i++)
                #pragma unroll
                for (int j = 0; j < TN; j++)
                    acc[i][j] = fmaf(ar[i], br[j], acc[i][j]);
        }
        __syncthreads();
    }

    const int c0 = colBase + tx * TN;
    float4 bv0 = *(const float4*)&bias[c0];
    float4 bv1 = *(const float4*)&bias[c0 + 4];
    const float bb[8] = {bv0.x, bv0.y, bv0.z, bv0.w, bv1.x, bv1.y, bv1.z, bv1.w};

    #pragma unroll
    for (int i = 0; i < TM; i++) {
        const int r = rowBase + ty * TM + i;
        float o[8];
        #pragma unroll
        for (int j = 0; j < TN; j++) {
            float v = acc[i][j] + bb[j];
            if (RELU) v = fmaxf(v, 0.f);
            o[j] = v;
        }
        *(float4*)&C[(size_t)r * N + c0]     = make_float4(o[0], o[1], o[2], o[3]);
        *(float4*)&C[(size_t)r * N + c0 + 4] = make_float4(o[4], o[5], o[6], o[7]);
    }
}

// ---------------- sims GEMM: out = (P @ E^T) / max(pn*en, eps) ----------------
// P: [M,K] row-major (K=256), E: [N,K] row-major
__global__ void __launch_bounds__(256, 2) sims_kernel(
    const float* __restrict__ P, const float* __restrict__ E,
    const float* __restrict__ pn, const float* __restrict__ en,
    float* __restrict__ out, int M, int N, int K)
{
    __shared__ float As[BK][BM];
    __shared__ float Ws[BK][BN];

    const int tid = threadIdx.x;
    const int tx = tid & 15;
    const int ty = tid >> 4;
    const int rowBase = blockIdx.y * BM;
    const int colBase = blockIdx.x * BN;

    const int aRow = tid >> 1;
    const int aCol = (tid & 1) * 4;
    const int gArow = rowBase + aRow;

    const int eRow = tid >> 1;           // local n: 0..127
    const int eCol = (tid & 1) * 4;      // k offset: 0 or 4
    const int gn = colBase + eRow;

    float acc[TM][TN];
    #pragma unroll
    for (int i = 0; i < TM; i++)
        #pragma unroll
        for (int j = 0; j < TN; j++) acc[i][j] = 0.f;

    for (int k0 = 0; k0 < K; k0 += BK) {
        float4 av = *(const float4*)&P[(size_t)gArow * K + k0 + aCol];
        As[aCol + 0][aRow] = av.x;
        As[aCol + 1][aRow] = av.y;
        As[aCol + 2][aRow] = av.z;
        As[aCol + 3][aRow] = av.w;

        float4 ev = make_float4(0.f, 0.f, 0.f, 0.f);
        if (gn < N) ev = *(const float4*)&E[(size_t)gn * K + k0 + eCol];
        Ws[eCol + 0][eRow] = ev.x;
        Ws[eCol + 1][eRow] = ev.y;
        Ws[eCol + 2][eRow] = ev.z;
        Ws[eCol + 3][eRow] = ev.w;

        __syncthreads();

        #pragma unroll
        for (int k = 0; k < BK; k++) {
            float ar[TM], br[TN];
            *(float4*)&ar[0] = *(const float4*)&As[k][ty * TM];
            *(float4*)&ar[4] = *(const float4*)&As[k][ty * TM + 4];
            *(float4*)&br[0] = *(const float4*)&Ws[k][tx * TN];
            *(float4*)&br[4] = *(const float4*)&Ws[k][tx * TN + 4];
            #pragma unroll
            for (int i = 0; i < TM; i++)
                #pragma unroll
                for (int j = 0; j < TN; j++)
                    acc[i][j] = fmaf(ar[i], br[j], acc[i][j]);
        }
        __syncthreads();
    }

    const int c0 = colBase + tx * TN;
    float enr[8];
    #pragma unroll
    for (int j = 0; j < TN; j++) {
        const int c = c0 + j;
        enr[j] = (c < N) ? en[c] : 1.f;
    }

    #pragma unroll
    for (int i = 0; i < TM; i++) {
        const int r = rowBase + ty * TM + i;
        const float rp = pn[r];
        #pragma unroll
        for (int j = 0; j < TN; j++) {
            const int c = c0 + j;
            if (c < N) {
                float denom = fmaxf(rp * enr[j], 1e-8f);
                out[(size_t)r * N + c] = acc[i][j] / denom;
            }
        }
    }
}

// ---------------- row L2 norms (cols = 256 fixed) ----------------
__global__ void row_norm_kernel(const float* __restrict__ X,
                                float* __restrict__ out, int rows)
{
    const int gw = (blockIdx.x * blockDim.x + threadIdx.x) >> 5;
    const int lane = threadIdx.x & 31;
    if (gw >= rows) return;
    const float4* x = (const float4*)(X + (size_t)gw * 256);
    float s = 0.f;
    #pragma unroll
    for (int i = 0; i < 2; i++) {
        float4 v = x[lane + i * 32];
        s += v.x * v.x + v.y * v.y + v.z * v.z + v.w * v.w;
    }
    #pragma unroll
    for (int o = 16; o; o >>= 1) s += __shfl_xor_sync(0xffffffffu, s, o);
    if (lane == 0) out[gw] = sqrtf(s);
}

// ---------------- top-5 per row, jax tie-break (lower index wins) ----------------
__global__ void __launch_bounds__(256) topk5_kernel(
    const float* __restrict__ sims, float* __restrict__ outIdx, int N)
{
    __shared__ float sv[5][256];
    __shared__ int   si[5][256];

    const int row = blockIdx.x;
    const int tid = threadIdx.x;
    const float* s = sims + (size_t)row * N;

    float v[5]; int id[5];
    #pragma unroll
    for (int k = 0; k < 5; k++) { v[k] = -CUDART_INF_F; id[k] = 0x7fffffff; }

    for (int j = tid; j < N; j += 256) {
        const float x = s[j];
        if (x > v[4] || (x == v[4] && j < id[4])) {
            float cv = x; int ci = j;
            #pragma unroll
            for (int p = 0; p < 5; p++) {
                const bool better = (cv > v[p]) || (cv == v[p] && ci < id[p]);
                const float tv = v[p]; const int ti = id[p];
                if (better) { v[p] = cv; id[p] = ci; cv = tv; ci = ti; }
            }
        }
    }

    #pragma unroll
    for (int k = 0; k < 5; k++) { sv[k][tid] = v[k]; si[k][tid] = id[k]; }
    __syncthreads();

    for (int str = 128; str > 0; str >>= 1) {
        if (tid < str) {
            int ia = 0, ib = 0;
            float mv[5]; int mi[5];
            #pragma unroll
            for (int k = 0; k < 5; k++) {
                const float va = sv[ia][tid];
                const float vb = sv[ib][tid + str];
                const int   xa = si[ia][tid];
                const int   xb = si[ib][tid + str];
                const bool takeA = (va > vb) || (va == vb && xa < xb);
                mv[k] = takeA ? va : vb;
                mi[k] = takeA ? xa : xb;
                if (takeA) ia++; else ib++;
            }
            #pragma unroll
            for (int k = 0; k < 5; k++) { sv[k][tid] = mv[k]; si[k][tid] = mi[k]; }
        }
        __syncthreads();
    }

    if (tid < 5) outIdx[(size_t)row * 5 + tid] = (float)si[tid][0];
}

// ---------------- launch ----------------
extern "C" void kernel_launch(void* const* d_in, const int* in_sizes, int n_in,
                              void* d_out, int out_size)
{
    const float* img = (const float*)d_in[0];   // [B,768]
    const float* txt = (const float*)d_in[1];   // [B,768]
    const float* W1  = (const float*)d_in[2];   // [1536,1024]
    const float* b1  = (const float*)d_in[3];   // [1024]
    const float* W2  = (const float*)d_in[4];   // [1024,512]
    const float* b2  = (const float*)d_in[5];   // [512]
    const float* W3  = (const float*)d_in[6];   // [512,256]
    const float* b3  = (const float*)d_in[7];   // [256]
    const float* emb = (const float*)d_in[8];   // [10000,256]

    const int B  = in_sizes[0] / 768;    // 8192
    const int N1 = in_sizes[3];          // 1024
    const int N2 = in_sizes[5];          // 512
    const int N3 = in_sizes[7];          // 256
    const int NE = in_sizes[8] / N3;     // 10000
    const int D  = 1536;

    float *h1, *h2, *p, *pn, *en;
    cudaGetSymbolAddress((void**)&h1, g_h1);
    cudaGetSymbolAddress((void**)&h2, g_h2);
    cudaGetSymbolAddress((void**)&p,  g_p);
    cudaGetSymbolAddress((void**)&pn, g_pn);
    cudaGetSymbolAddress((void**)&en, g_en);

    float* out = (float*)d_out;
    float* outIdx = out + (size_t)B * NE;

    // Layer 1 (concat folded into loader) -> h1
    {
        dim3 grid(N1 / BN, B / BM);
        gemm_bias_kernel<true, true><<<grid, 256>>>(img, txt, W1, b1, h1, B, N1, D);
    }
    // Layer 2 -> h2
    {
        dim3 grid(N2 / BN, B / BM);
        gemm_bias_kernel<true, false><<<grid, 256>>>(h1, nullptr, W2, b2, h2, B, N2, N1);
    }
    // Layer 3 (no relu) -> p
    {
        dim3 grid(N3 / BN, B / BM);
        gemm_bias_kernel<false, false><<<grid, 256>>>(h2, nullptr, W3, b3, p, B, N3, N2);
    }
    // Norms
    {
        int threads = 256;
        int warpsPerBlock = threads / 32;
        row_norm_kernel<<<(B  + warpsPerBlock - 1) / warpsPerBlock, threads>>>(p,   pn, B);
        row_norm_kernel<<<(NE + warpsPerBlock - 1) / warpsPerBlock, threads>>>(emb, en, NE);
    }
    // Sims
    {
        dim3 grid((NE + BN - 1) / BN, B / BM);
        sims_kernel<<<grid, 256>>>(p, emb, pn, en, out, B, NE, N3);
    }
    // Top-5 indices
    topk5_kernel<<<B, 256>>>(out, outIdx, NE);
}